// round 15
// baseline (speedup 1.0000x reference)
#include <cuda_runtime.h>
#include <cstdint>

#define KCAP 8
#define NKP 15
#define OC 64
#define XD 12
#define NMOM 91            // cnt(1) + Sx(12) + Sxx upper-tri(78)
#define SENT 0x7FFFFFFF
#define NVOX_TOT 87040     // 65536 + 16384 + 4096 + 1024
#define NSLOT_TOT (NVOX_TOT * KCAP)
#define NB_VOX (NVOX_TOT / 256)    // 340 blocks in k_voxstats

// per-scale voxel offsets (cumulative V); also active-list and output-plane offsets
__device__ __constant__ int c_VOFF[5] = {0, 65536, 81920, 86016, 87040};
// upper-triangle (a,b) pairs for XD=12 second moments — __device__ (LDG path)
__device__ const signed char d_triA[78] = {
    0,0,0,0,0,0,0,0,0,0,0,0, 1,1,1,1,1,1,1,1,1,1,1, 2,2,2,2,2,2,2,2,2,2,
    3,3,3,3,3,3,3,3,3, 4,4,4,4,4,4,4,4, 5,5,5,5,5,5,5, 6,6,6,6,6,6,
    7,7,7,7,7, 8,8,8,8, 9,9,9, 10,10, 11};
__device__ const signed char d_triB[78] = {
    0,1,2,3,4,5,6,7,8,9,10,11, 1,2,3,4,5,6,7,8,9,10,11, 2,3,4,5,6,7,8,9,10,11,
    3,4,5,6,7,8,9,10,11, 4,5,6,7,8,9,10,11, 5,6,7,8,9,10,11, 6,7,8,9,10,11,
    7,8,9,10,11, 8,9,10,11, 9,10,11, 10,11, 11};

// ---------------- device scratch (static, no allocs) ----------------
__device__ int      g_slots[NSLOT_TOT];
__device__ float    g_cent[NVOX_TOT * 3];
__device__ int      g_npts[NVOX_TOT];
__device__ int      g_active[NVOX_TOT];      // per-scale regions at c_VOFF
__device__ int      g_actidx[NVOX_TOT];      // -1 or active-list position
__device__ int      g_nactive[4];
__device__ double   g_mom[4 * 92];           // double atomic accumulate
__device__ float    g_out[(size_t)NVOX_TOT * OC];
__device__ float    g_zval[(size_t)NVOX_TOT * OC];
__device__ float    g_fill[4 * OC];
__device__ unsigned g_done;                  // ticket; atomicInc wrap self-resets to 0

// ---------------- kernel 1: init (int4-wide) ----------------
__global__ void k_init() {
    int i = blockIdx.x * blockDim.x + threadIdx.x;
    if (i < NSLOT_TOT / 4)
        reinterpret_cast<int4*>(g_slots)[i] = make_int4(SENT, SENT, SENT, SENT);
    if (i < NVOX_TOT / 4)
        reinterpret_cast<int4*>(g_actidx)[i] = make_int4(-1, -1, -1, -1);
    if (i < 4 * 92) g_mom[i] = 0.0;
    if (i < 4) g_nactive[i] = 0;
}

// ---------------- kernel 2: fused 4-scale insert (first-K by original index) ----------------
__global__ void k_insert(const float* __restrict__ pts, int N) {
    int i = blockIdx.x * blockDim.x + threadIdx.x;
    if (i >= N) return;
    float x = pts[i * 5 + 0], y = pts[i * 5 + 1], z = pts[i * 5 + 2];
    if (!(z >= -5.0f && z < 3.0f)) return;
    float bx = x + 51.2f, by = y + 51.2f;
    int G = 256;
    float vs = 0.4f;
    #pragma unroll
    for (int s = 0; s < 4; s++) {
        float fx = floorf(bx / vs), fy = floorf(by / vs);
        if (fx >= 0.f && fy >= 0.f && fx < (float)G && fy < (float)G) {
            int ix = (int)fx, iy = (int)fy;
            int* sl = &g_slots[(c_VOFF[s] + iy * G + ix) * KCAP];
            int val = i;
            #pragma unroll
            for (int k = 0; k < KCAP; k++) {
                int cur = sl[k];            // racy pre-check OK: slot values only decrease
                if (cur < val) continue;
                int old = atomicMin(&sl[k], val);
                if (old == SENT) break;
                val = max(val, old);
            }
        }
        G >>= 1;
        vs *= 2.0f;
    }
}

// ---------------- kernel 3: voxstats + last-block active pipeline ----------------
__global__ void __launch_bounds__(256) k_voxstats(
        const float* __restrict__ pts, const float* __restrict__ kp,
        const float* __restrict__ kpw, const float* __restrict__ w_pre,
        const float* __restrict__ b_pre, const float* __restrict__ g_pre,
        const float* __restrict__ be_pre,
        const float* __restrict__ w_post, const float* __restrict__ b_post,
        const float* __restrict__ g_post, const float* __restrict__ be_post) {
    __shared__ float skp[NKP * 3];
    __shared__ float sAcc[NMOM];
    __shared__ float sw[XD * OC];
    __shared__ float ss[NKP * OC];
    __shared__ bool  amLast;
    int t = threadIdx.x, lane = t & 31;
    if (t < NKP * 3) skp[t] = kp[t];
    if (t < NMOM) sAcc[t] = 0.f;
    __syncthreads();

    int gv = blockIdx.x * 256 + t;              // global voxel index (all scales)
    {
        int s = (gv < 65536) ? 0 : (gv < 81920) ? 1 : (gv < 86016) ? 2 : 3;
        int v = gv - c_VOFF[s];
        int G = 256 >> s;
        float vs = 0.4f * (float)(1 << s);
        const int* sl = &g_slots[gv * KCAP];
        float ax = (float)(v & (G - 1)) + vs * 0.5f;
        float ay = (float)(v >> (8 - s)) + vs * 0.5f;

        // pass 1: gather all 5 floats per slot into registers, count/centroid/active
        int idxs[KCAP];
        float px[KCAP], py[KCAP], pz[KCAP], pf0[KCAP], pf1[KCAP];
        int cnt = 0;
        float sx = 0.f, sy = 0.f, sz = 0.f;
        bool act = false;
        #pragma unroll
        for (int k = 0; k < KCAP; k++) {
            int idx = sl[k];
            idxs[k] = idx;
            px[k] = py[k] = pz[k] = pf0[k] = pf1[k] = 0.f;
            if (idx == SENT) continue;
            float a  = __ldg(&pts[idx * 5 + 0]);
            float b  = __ldg(&pts[idx * 5 + 1]);
            float c  = __ldg(&pts[idx * 5 + 2]);
            float f0 = __ldg(&pts[idx * 5 + 3]);
            float f1 = __ldg(&pts[idx * 5 + 4]);
            px[k] = a; py[k] = b; pz[k] = c; pf0[k] = f0; pf1[k] = f1;
            sx += a; sy += b; sz += c; cnt++;
            if (!act) {
                float dx = a - ax, dy = b - ay, dz = c - 4.0f;
                #pragma unroll
                for (int q = 0; q < NKP; q++) {
                    float ex = dx - skp[q * 3 + 0];
                    float ey = dy - skp[q * 3 + 1];
                    float ez = dz - skp[q * 3 + 2];
                    if (ex * ex + ey * ey + ez * ez < 1.0f) { act = true; break; }
                }
            }
        }
        g_npts[gv] = cnt;
        float nf = (float)max(cnt, 1);
        float cx = sx / nf, cy = sy / nf, cz = sz / nf;
        g_cent[gv * 3 + 0] = cx;
        g_cent[gv * 3 + 1] = cy;
        g_cent[gv * 3 + 2] = cz;
        if (act) {
            int p = atomicAdd(&g_nactive[s], 1);
            g_active[c_VOFF[s] + p] = v;
            g_actidx[gv] = p;
        }

        // pass 2: moments from registers — zero extra LDG
        float m1[XD];
        float m2[78];
        #pragma unroll
        for (int i2 = 0; i2 < XD; i2++) m1[i2] = 0.f;
        #pragma unroll
        for (int i2 = 0; i2 < 78; i2++) m2[i2] = 0.f;
        float n = (float)cnt;
        #pragma unroll
        for (int k = 0; k < KCAP; k++) {
            if (idxs[k] == SENT) continue;
            float x[XD];
            x[0] = pf0[k]; x[1] = pf1[k];
            x[2] = px[k] - ax; x[3] = py[k] - ay; x[4] = pz[k] - 4.0f;
            x[5] = px[k] - cx; x[6] = py[k] - cy; x[7] = pz[k] - cz;
            x[8] = cx; x[9] = cy; x[10] = cz; x[11] = n;
            #pragma unroll
            for (int i2 = 0; i2 < XD; i2++) m1[i2] += x[i2];
            int j = 0;
            #pragma unroll
            for (int a2 = 0; a2 < XD; a2++)
                #pragma unroll
                for (int b2 = a2; b2 < XD; b2++) { m2[j] += x[a2] * x[b2]; j++; }
        }

        {
            float val = (float)cnt;
            #pragma unroll
            for (int o = 16; o; o >>= 1) val += __shfl_xor_sync(0xffffffffu, val, o);
            if (lane == 0) atomicAdd(&sAcc[0], val);
        }
        #pragma unroll
        for (int i2 = 0; i2 < XD; i2++) {
            float val = m1[i2];
            #pragma unroll
            for (int o = 16; o; o >>= 1) val += __shfl_xor_sync(0xffffffffu, val, o);
            if (lane == 0) atomicAdd(&sAcc[1 + i2], val);
        }
        #pragma unroll
        for (int i2 = 0; i2 < 78; i2++) {
            float val = m2[i2];
            #pragma unroll
            for (int o = 16; o; o >>= 1) val += __shfl_xor_sync(0xffffffffu, val, o);
            if (lane == 0) atomicAdd(&sAcc[13 + i2], val);
        }
        __syncthreads();
        if (t < NMOM) atomicAdd(&g_mom[s * 92 + t], (double)sAcc[t]);
    }

    // ---- ticket: last block runs the active-voxel pipeline ----
    __syncthreads();
    __threadfence();
    if (t == 0) {
        unsigned old = atomicInc(&g_done, NB_VOX - 1);   // wraps to 0: self-reset
        amLast = (old == NB_VOX - 1);
    }
    __syncthreads();
    if (!amLast) return;
    __threadfence();

    for (int i = t; i < XD * OC; i += 256) sw[i] = w_pre[i];
    __syncthreads();

    int c = t;                                   // channel when t < OC
    for (int s = 0; s < 4; s++) {
        // per-channel pre-BN from the global moments
        float ym = 0.f, al = 0.f, be = 0.f, bp = 0.f;
        if (t < OC) {
            be = be_pre[c]; bp = b_pre[c];
            const double* mom = &g_mom[s * 92];
            float cntf = (float)mom[0];
            float sxw = 0.f;
            #pragma unroll
            for (int i = 0; i < XD; i++) sxw += (float)mom[1 + i] * sw[i * OC + c];
            float qv = 0.f;
            for (int j = 0; j < 78; j++) {
                int a = d_triA[j], b = d_triB[j];
                float term = (float)mom[13 + j] * sw[a * OC + c] * sw[b * OC + c];
                qv += (a == b) ? term : 2.0f * term;
            }
            double cnt = (double)cntf;
            double den = cnt > 1.0 ? cnt : 1.0;
            double b = (double)bp;
            double ymd = ((double)sxw + cnt * b) / den;
            double Ey2 = ((double)qv + 2.0 * b * (double)sxw + cnt * b * b) / den;
            double var = Ey2 - ymd * ymd;
            if (var < 0) var = 0;
            ym = (float)ymd;
            al = (float)((double)g_pre[c] / sqrt(var + 1e-5));
        }
        int G = 256 >> s;
        float vs = 0.4f * (float)(1 << s);
        int voff = c_VOFF[s];
        int n = g_nactive[s];
        // KP conv per active voxel (serial; n is tiny)
        for (int i = 0; i < n; i++) {
            int v = g_active[voff + i];
            int gv2 = voff + v;
            float sreg[NKP];
            unsigned kmask = 0;
            if (t < OC) {
                #pragma unroll
                for (int q = 0; q < NKP; q++) sreg[q] = 0.f;
                float cx = g_cent[gv2 * 3 + 0], cy = g_cent[gv2 * 3 + 1], cz = g_cent[gv2 * 3 + 2];
                float nn = (float)g_npts[gv2];
                float ax = (float)(v & (G - 1)) + vs * 0.5f;
                float ay = (float)(v >> (8 - s)) + vs * 0.5f;
                for (int k = 0; k < KCAP; k++) {
                    int idx = g_slots[gv2 * KCAP + k];
                    if (idx == SENT) continue;
                    float a  = __ldg(&pts[idx * 5 + 0]);
                    float b  = __ldg(&pts[idx * 5 + 1]);
                    float zc = __ldg(&pts[idx * 5 + 2]);
                    float f0 = __ldg(&pts[idx * 5 + 3]);
                    float f1 = __ldg(&pts[idx * 5 + 4]);
                    float x[XD];
                    x[0] = f0; x[1] = f1;
                    x[2] = a - ax; x[3] = b - ay; x[4] = zc - 4.0f;
                    x[5] = a - cx; x[6] = b - cy; x[7] = zc - cz;
                    x[8] = cx; x[9] = cy; x[10] = cz; x[11] = nn;
                    float y = bp;
                    #pragma unroll
                    for (int q2 = 0; q2 < XD; q2++) y += x[q2] * sw[q2 * OC + c];
                    y = (y - ym) * al + be;
                    y = fmaxf(y, 0.f);
                    float dx = x[2], dy = x[3], dz = x[4];
                    #pragma unroll
                    for (int q = 0; q < NKP; q++) {
                        float ex = dx - skp[q * 3 + 0];
                        float ey = dy - skp[q * 3 + 1];
                        float ez = dz - skp[q * 3 + 2];
                        float d2 = ex * ex + ey * ey + ez * ez;
                        float h = 1.0f - sqrtf(d2 + 1e-12f);
                        if (h > 0.f) { sreg[q] += h * y; kmask |= (1u << q); }
                    }
                }
                #pragma unroll
                for (int q = 0; q < NKP; q++) ss[q * OC + c] = sreg[q];
            }
            __syncthreads();
            if (t < OC) {
                float acc = 0.f;
                for (int q = 0; q < NKP; q++) {
                    if (!((kmask >> q) & 1)) continue;
                    #pragma unroll 8
                    for (int c2 = 0; c2 < OC; c2++)
                        acc += ss[q * OC + c2] * __ldg(&kpw[(q * OC + c2) * OC + c]);
                }
                g_out[(size_t)(voff + i) * OC + c] = acc;
            }
            __syncthreads();
        }
        // post-BN stats + finalize + z values
        if (t < OC) {
            float m1v = 0.f, qv = 0.f;
            for (int i = 0; i < n; i++) {
                const float* row = &g_out[(size_t)(voff + i) * OC];
                float dot = 0.f;
                #pragma unroll 8
                for (int k = 0; k < OC; k++) dot += row[k] * __ldg(&w_post[k * OC + c]);
                m1v += dot;
                qv  += dot * dot;
            }
            int V = (256 >> s) * (256 >> s);
            double bb = (double)b_post[c];
            double Vd = (double)V;
            double mean = (double)m1v / Vd + bb;
            double Ez2 = ((double)qv + 2.0 * bb * (double)m1v) / Vd + bb * bb;
            double var = Ez2 - mean * mean;
            if (var < 0) var = 0;
            double alpha = (double)g_post[c] / sqrt(var + 1e-5);
            float pm = (float)mean, pa = (float)alpha, bep = be_post[c];
            g_fill[s * OC + c] = fmaxf((float)((bb - mean) * alpha + (double)bep), 0.f);
            for (int i = 0; i < n; i++) {
                const float* row = &g_out[(size_t)(voff + i) * OC];
                float dot = 0.f;
                #pragma unroll 8
                for (int k = 0; k < OC; k++) dot += row[k] * __ldg(&w_post[k * OC + c]);
                float z = dot + (float)bb;
                g_zval[(size_t)(voff + i) * OC + c] = fmaxf((z - pm) * pa + bep, 0.f);
            }
        }
        __syncthreads();   // before ss reuse next scale
    }
}

// ---------------- kernel 4: fill + scatter in one pass (vectorized) ----------------
__global__ void k_fillscatter(float4* __restrict__ out4) {
    int e = blockIdx.x * blockDim.x + threadIdx.x;     // float4 units, total 1,392,640
    if (e >= 1392640) return;
    int s, off, sh;
    if (e < 1048576)       { s = 0; off = 0;       sh = 14; }
    else if (e < 1310720)  { s = 1; off = 1048576; sh = 12; }
    else if (e < 1376256)  { s = 2; off = 1310720; sh = 10; }
    else                   { s = 3; off = 1376256; sh = 8;  }
    int rel = e - off;
    int c = rel >> sh;
    float f = g_fill[s * OC + c];
    float4 val = make_float4(f, f, f, f);
    if (g_nactive[s] > 0) {                            // fast path: skip actidx read
        int v = (rel & ((1 << sh) - 1)) << 2;          // first of 4 voxels
        int gv = c_VOFF[s] + v;
        int4 ai = *reinterpret_cast<const int4*>(&g_actidx[gv]);   // gv % 4 == 0
        if (ai.x >= 0 || ai.y >= 0 || ai.z >= 0 || ai.w >= 0) {
            size_t zb = (size_t)c_VOFF[s] * OC + c;
            if (ai.x >= 0) val.x = g_zval[zb + (size_t)ai.x * OC];
            if (ai.y >= 0) val.y = g_zval[zb + (size_t)ai.y * OC];
            if (ai.z >= 0) val.z = g_zval[zb + (size_t)ai.z * OC];
            if (ai.w >= 0) val.w = g_zval[zb + (size_t)ai.w * OC];
        }
    }
    out4[e] = val;
}

// ---------------- launcher ----------------
extern "C" void kernel_launch(void* const* d_in, const int* in_sizes, int n_in,
                              void* d_out, int out_size) {
    const float* pts     = (const float*)d_in[0];
    const float* kp      = (const float*)d_in[1];
    const float* w_pre   = (const float*)d_in[2];
    const float* b_pre   = (const float*)d_in[3];
    const float* g_pre   = (const float*)d_in[4];
    const float* be_pre  = (const float*)d_in[5];
    const float* kpw     = (const float*)d_in[6];
    const float* w_post  = (const float*)d_in[7];
    const float* b_post  = (const float*)d_in[8];
    const float* g_post  = (const float*)d_in[9];
    const float* be_post = (const float*)d_in[10];
    float* out = (float*)d_out;
    int N = in_sizes[0] / 5;

    k_init       <<<(NSLOT_TOT / 4 + 255) / 256, 256>>>();
    if (N > 0) k_insert<<<(N + 255) / 256, 256>>>(pts, N);
    k_voxstats   <<<NB_VOX, 256>>>(pts, kp, kpw, w_pre, b_pre, g_pre, be_pre,
                                   w_post, b_post, g_post, be_post);
    k_fillscatter<<<(1392640 + 255) / 256, 256>>>((float4*)out);
}